// round 5
// baseline (speedup 1.0000x reference)
#include <cuda_runtime.h>
#include <cstdint>
#include <math.h>

#define BB 8
#define TT 512
#define CC 512
#define HH 8
#define DH 64
#define CF 2048
#define MTOK (BB*TT)      // 4096
#define VV 512
#define NSTEPS 4
#define ATT_SCALE 0.125f  // 1/sqrt(64)
#define C3 (3*CC)         // 1536

// ---------------- scratch (device globals: no allocations allowed) ----------
__device__ float g_x  [MTOK*CC];
__device__ float g_xn [MTOK*CC];
__device__ float g_qkv[MTOK*C3];
__device__ float g_y  [MTOK*CC];
__device__ float g_h  [MTOK*CF];
// pre-rounded (tf32) weights
__device__ float g_wqkv[2*CC*C3];
__device__ float g_bqkv[2*C3];
__device__ float g_wp  [2*CC*CC];
__device__ float g_w1  [2*CC*CF];
__device__ float g_w2  [2*CF*CC];
__device__ float g_wh  [CC*VV];

// ======================= helpers ==============================
__device__ __forceinline__ uint32_t smem_u32(const void* p) {
    uint32_t a;
    asm("{ .reg .u64 t; cvta.to.shared.u64 t, %1; cvt.u32.u64 %0, t; }"
        : "=r"(a) : "l"(p));
    return a;
}
__device__ __forceinline__ void cp_async16(uint32_t dst, const void* src) {
    asm volatile("cp.async.cg.shared.global [%0], [%1], 16;" :: "r"(dst), "l"(src));
}
__device__ __forceinline__ void cp_commit() {
    asm volatile("cp.async.commit_group;" ::: "memory");
}
template <int N>
__device__ __forceinline__ void cp_wait() {
    asm volatile("cp.async.wait_group %0;" :: "n"(N) : "memory");
}
__device__ __forceinline__ uint32_t f2tf32(float x) {
    uint32_t r;
    asm("cvt.rna.tf32.f32 %0, %1;" : "=r"(r) : "f"(x));
    return r;
}
__device__ __forceinline__ float rndf(float x) { return __uint_as_float(f2tf32(x)); }
// D += A @ B  (m16n8k8, tf32 in, fp32 accumulate)
__device__ __forceinline__ void mma8(float* c, const uint32_t* a, const uint32_t* b) {
    asm volatile(
        "mma.sync.aligned.m16n8k8.row.col.f32.tf32.tf32.f32 "
        "{%0,%1,%2,%3}, {%4,%5,%6,%7}, {%8,%9}, {%0,%1,%2,%3};"
        : "+f"(c[0]), "+f"(c[1]), "+f"(c[2]), "+f"(c[3])
        : "r"(a[0]), "r"(a[1]), "r"(a[2]), "r"(a[3]), "r"(b[0]), "r"(b[1]));
}

// ---------------- weight preprocessing (once per launch, trivial cost) -----
__global__ void prep_wqkv_k(const float* __restrict__ Wq, const float* __restrict__ Wk,
                            const float* __restrict__ Wv) {
    int i = blockIdx.x * 256 + threadIdx.x;          // over 2*CC*CC
    if (i >= 2 * CC * CC) return;
    int l = i / (CC * CC), rem = i % (CC * CC);
    int k = rem / CC, n = rem % CC;
    size_t d = ((size_t)l * CC + k) * C3;
    g_wqkv[d + n]          = rndf(Wq[i]);
    g_wqkv[d + CC + n]     = rndf(Wk[i]);
    g_wqkv[d + 2 * CC + n] = rndf(Wv[i]);
}
__global__ void prep_bqkv_k(const float* __restrict__ bq, const float* __restrict__ bk,
                            const float* __restrict__ bv) {
    int i = blockIdx.x * 256 + threadIdx.x;          // over 2*CC
    if (i >= 2 * CC) return;
    int l = i / CC, n = i % CC;
    g_bqkv[l * C3 + n]          = bq[i];
    g_bqkv[l * C3 + CC + n]     = bk[i];
    g_bqkv[l * C3 + 2 * CC + n] = bv[i];
}
__global__ void prep_round_k(const float* __restrict__ src, float* __restrict__ dst, int n) {
    int i = blockIdx.x * 256 + threadIdx.x;
    if (i < n) dst[i] = rndf(src[i]);
}

// ================== dense GEMM: out = epi(A@W + bias + res) ================
// A[M,K] row-major pre-rounded tf32; W[K,N] row-major pre-rounded tf32.
// CTA tile 128x128, 8 warps (2x4), warp tile 64x32, K-chunk 32, double buffer.
#define AS_STR 36
#define BS_STR 136
#define GEMM_SMEM (2*128*AS_STR*4 + 2*32*BS_STR*4)   // 71680 B

template <bool GELU, bool ROUND>
__global__ void __launch_bounds__(256, 2)
mma_gemm_k(const float* __restrict__ A, const float* __restrict__ W,
           const float* __restrict__ bias, const float* __restrict__ res,
           float* __restrict__ out, int M, int N, int K) {
    extern __shared__ char dsm[];
    float* As = (float*)dsm;                       // [2][128][AS_STR]
    float* Bs = As + 2 * 128 * AS_STR;             // [2][32][BS_STR]

    int tid = threadIdx.x;
    int wid = tid >> 5, lane = tid & 31;
    int g = lane >> 2, t = lane & 3;
    int mw = wid >> 2, nw = wid & 3;               // warp grid 2x4
    int m0 = blockIdx.y * 128, n0 = blockIdx.x * 128;

    auto loadA = [&](int chunk, int buf) {
        const float* src = A + (size_t)m0 * K + chunk * 32;
        float* dst = As + buf * 128 * AS_STR;
        #pragma unroll
        for (int i = 0; i < 4; i++) {
            int c = tid + i * 256;
            int m = c >> 3, s = c & 7;
            cp_async16(smem_u32(dst + m * AS_STR + s * 4),
                       src + (size_t)m * K + s * 4);
        }
    };
    auto loadB = [&](int chunk, int buf) {
        const float* src = W + (size_t)(chunk * 32) * N + n0;
        float* dst = Bs + buf * 32 * BS_STR;
        #pragma unroll
        for (int i = 0; i < 4; i++) {
            int c = tid + i * 256;
            int k = c >> 5, s = c & 31;
            cp_async16(smem_u32(dst + k * BS_STR + s * 4),
                       src + (size_t)k * N + s * 4);
        }
    };

    float acc[4][4][4];
    #pragma unroll
    for (int mi = 0; mi < 4; mi++)
        #pragma unroll
        for (int ni = 0; ni < 4; ni++)
            #pragma unroll
            for (int q = 0; q < 4; q++) acc[mi][ni][q] = 0.0f;

    const int nch = K >> 5;
    loadA(0, 0); loadB(0, 0); cp_commit();

    for (int i = 0; i < nch; i++) {
        int buf = i & 1;
        if (i + 1 < nch) {
            loadA(i + 1, buf ^ 1); loadB(i + 1, buf ^ 1); cp_commit();
            cp_wait<1>();
        } else {
            cp_wait<0>();
        }
        __syncthreads();
        const float* Ab = As + buf * 128 * AS_STR;
        const float* Bb = Bs + buf * 32 * BS_STR;
        #pragma unroll
        for (int ks = 0; ks < 4; ks++) {
            int k0 = ks * 8;
            uint32_t af[4][4], bf[4][2];
            #pragma unroll
            for (int mi = 0; mi < 4; mi++) {
                int row = mw * 64 + mi * 16;
                af[mi][0] = __float_as_uint(Ab[(row + g)     * AS_STR + k0 + t]);
                af[mi][1] = __float_as_uint(Ab[(row + 8 + g) * AS_STR + k0 + t]);
                af[mi][2] = __float_as_uint(Ab[(row + g)     * AS_STR + k0 + t + 4]);
                af[mi][3] = __float_as_uint(Ab[(row + 8 + g) * AS_STR + k0 + t + 4]);
            }
            #pragma unroll
            for (int ni = 0; ni < 4; ni++) {
                int col = nw * 32 + ni * 8 + g;
                bf[ni][0] = __float_as_uint(Bb[(k0 + t)     * BS_STR + col]);
                bf[ni][1] = __float_as_uint(Bb[(k0 + t + 4) * BS_STR + col]);
            }
            #pragma unroll
            for (int mi = 0; mi < 4; mi++)
                #pragma unroll
                for (int ni = 0; ni < 4; ni++)
                    mma8(acc[mi][ni], af[mi], bf[ni]);
        }
        __syncthreads();
    }

    // epilogue
    #pragma unroll
    for (int mi = 0; mi < 4; mi++) {
        #pragma unroll
        for (int ni = 0; ni < 4; ni++) {
            int r0  = m0 + mw * 64 + mi * 16 + g;
            int col = n0 + nw * 32 + ni * 8 + 2 * t;
            #pragma unroll
            for (int hh = 0; hh < 2; hh++) {
                int r = r0 + 8 * hh;
                #pragma unroll
                for (int q = 0; q < 2; q++) {
                    float v = acc[mi][ni][2 * hh + q];
                    int c = col + q;
                    if (bias) v += bias[c];
                    if (res)  v += res[(size_t)r * N + c];
                    if (GELU) v = 0.5f * v * (1.0f + erff(v * 0.70710678118654752f));
                    if (ROUND) v = rndf(v);
                    out[(size_t)r * N + c] = v;
                }
            }
        }
    }
}

// ================== flash attention: per (b,h,qtile=128) ==================
// Q[128,64] vs K/V chunks of 128 rows. 8 warps, each owns 16 query rows.
#define QK_STR 68
#define V_STR  72
#define P_STR  132
#define FL_SMEM ((2*128*QK_STR + 128*V_STR + 128*P_STR) * 4)   // 174080 B

__global__ void __launch_bounds__(256)
flash_k() {
    extern __shared__ float fsm[];
    float* Qs = fsm;                    // [128][68]
    float* Ks = Qs + 128 * QK_STR;      // [128][68]
    float* Vs = Ks + 128 * QK_STR;      // [128][72]
    float* Ps = Vs + 128 * V_STR;       // [128][132]

    int tid = threadIdx.x;
    int w = tid >> 5, lane = tid & 31;
    int g = lane >> 2, t = lane & 3;
    int z = blockIdx.y;                 // b*H + h
    int b = z >> 3, h = z & 7;
    int qt = blockIdx.x * 128;

    const float* qbase = g_qkv + ((size_t)(b * TT + qt)) * C3 + h * DH;
    const float* kbase = g_qkv + ((size_t)(b * TT)) * C3 + CC + h * DH;
    const float* vbase = g_qkv + ((size_t)(b * TT)) * C3 + 2 * CC + h * DH;

    // Q: 128 rows x 16 segs of 16B = 2048 tasks
    #pragma unroll
    for (int i = 0; i < 8; i++) {
        int c = tid + i * 256;
        int r = c >> 4, s = c & 15;
        cp_async16(smem_u32(Qs + r * QK_STR + s * 4),
                   qbase + (size_t)r * C3 + s * 4);
    }
    cp_commit();

    float m0 = -1e30f, m1 = -1e30f, l0 = 0.0f, l1 = 0.0f;
    float o[8][4];
    #pragma unroll
    for (int nf = 0; nf < 8; nf++)
        #pragma unroll
        for (int q = 0; q < 4; q++) o[nf][q] = 0.0f;

    for (int kc = 0; kc < 4; kc++) {
        __syncthreads();                // prior chunk done with Ks/Vs
        #pragma unroll
        for (int i = 0; i < 8; i++) {
            int c = tid + i * 256;
            int r = c >> 4, s = c & 15;
            cp_async16(smem_u32(Ks + r * QK_STR + s * 4),
                       kbase + (size_t)(kc * 128 + r) * C3 + s * 4);
            cp_async16(smem_u32(Vs + r * V_STR + s * 4),
                       vbase + (size_t)(kc * 128 + r) * C3 + s * 4);
        }
        cp_commit(); cp_wait<0>();
        __syncthreads();

        // ---- S = (Q K^T) * scale : 16 n-fragments of 8 cols ----
        float s[16][4];
        #pragma unroll
        for (int nf = 0; nf < 16; nf++)
            #pragma unroll
            for (int q = 0; q < 4; q++) s[nf][q] = 0.0f;
        #pragma unroll
        for (int ks = 0; ks < 8; ks++) {
            int k0 = ks * 8;
            uint32_t af[4];
            af[0] = __float_as_uint(Qs[(w * 16 + g)     * QK_STR + k0 + t]);
            af[1] = __float_as_uint(Qs[(w * 16 + 8 + g) * QK_STR + k0 + t]);
            af[2] = __float_as_uint(Qs[(w * 16 + g)     * QK_STR + k0 + t + 4]);
            af[3] = __float_as_uint(Qs[(w * 16 + 8 + g) * QK_STR + k0 + t + 4]);
            #pragma unroll
            for (int nf = 0; nf < 16; nf++) {
                int col = nf * 8 + g;
                uint32_t bf[2];
                bf[0] = __float_as_uint(Ks[col * QK_STR + k0 + t]);
                bf[1] = __float_as_uint(Ks[col * QK_STR + k0 + t + 4]);
                mma8(s[nf], af, bf);
            }
        }
        // ---- online softmax ----
        float cm0 = -1e30f, cm1 = -1e30f;
        #pragma unroll
        for (int nf = 0; nf < 16; nf++) {
            s[nf][0] *= ATT_SCALE; s[nf][1] *= ATT_SCALE;
            s[nf][2] *= ATT_SCALE; s[nf][3] *= ATT_SCALE;
            cm0 = fmaxf(cm0, fmaxf(s[nf][0], s[nf][1]));
            cm1 = fmaxf(cm1, fmaxf(s[nf][2], s[nf][3]));
        }
        cm0 = fmaxf(cm0, __shfl_xor_sync(0xffffffffu, cm0, 1));
        cm0 = fmaxf(cm0, __shfl_xor_sync(0xffffffffu, cm0, 2));
        cm1 = fmaxf(cm1, __shfl_xor_sync(0xffffffffu, cm1, 1));
        cm1 = fmaxf(cm1, __shfl_xor_sync(0xffffffffu, cm1, 2));
        float mn0 = fmaxf(m0, cm0), mn1 = fmaxf(m1, cm1);
        float cr0 = expf(m0 - mn0), cr1 = expf(m1 - mn1);
        l0 *= cr0; l1 *= cr1;
        #pragma unroll
        for (int nf = 0; nf < 8; nf++) {
            o[nf][0] *= cr0; o[nf][1] *= cr0;
            o[nf][2] *= cr1; o[nf][3] *= cr1;
        }
        m0 = mn0; m1 = mn1;
        float rs0 = 0.0f, rs1 = 0.0f;
        #pragma unroll
        for (int nf = 0; nf < 16; nf++) {
            s[nf][0] = expf(s[nf][0] - mn0); s[nf][1] = expf(s[nf][1] - mn0);
            s[nf][2] = expf(s[nf][2] - mn1); s[nf][3] = expf(s[nf][3] - mn1);
            rs0 += s[nf][0] + s[nf][1];
            rs1 += s[nf][2] + s[nf][3];
        }
        rs0 += __shfl_xor_sync(0xffffffffu, rs0, 1);
        rs0 += __shfl_xor_sync(0xffffffffu, rs0, 2);
        rs1 += __shfl_xor_sync(0xffffffffu, rs1, 1);
        rs1 += __shfl_xor_sync(0xffffffffu, rs1, 2);
        l0 += rs0; l1 += rs1;

        // ---- P -> SMEM (rounded tf32), warp-private rows ----
        #pragma unroll
        for (int nf = 0; nf < 16; nf++) {
            int col = nf * 8 + 2 * t;
            Ps[(w * 16 + g)     * P_STR + col]     = rndf(s[nf][0]);
            Ps[(w * 16 + g)     * P_STR + col + 1] = rndf(s[nf][1]);
            Ps[(w * 16 + 8 + g) * P_STR + col]     = rndf(s[nf][2]);
            Ps[(w * 16 + 8 + g) * P_STR + col + 1] = rndf(s[nf][3]);
        }
        __syncwarp();

        // ---- O += P @ V ----
        #pragma unroll
        for (int ks = 0; ks < 16; ks++) {
            int k0 = ks * 8;
            uint32_t af[4];
            af[0] = __float_as_uint(Ps[(w * 16 + g)     * P_STR + k0 + t]);
            af[1] = __float_as_uint(Ps[(w * 16 + 8 + g) * P_STR + k0 + t]);
            af[2] = __float_as_uint(Ps[(w * 16 + g)     * P_STR + k0 + t + 4]);
            af[3] = __float_as_uint(Ps[(w * 16 + 8 + g) * P_STR + k0 + t + 4]);
            #pragma unroll
            for (int nf = 0; nf < 8; nf++) {
                int col = nf * 8 + g;
                uint32_t bf[2];
                bf[0] = __float_as_uint(Vs[(k0 + t)     * V_STR + col]);
                bf[1] = __float_as_uint(Vs[(k0 + t + 4) * V_STR + col]);
                mma8(o[nf], af, bf);
            }
        }
    }

    // ---- write y = O / l (rounded, feeds proj GEMM) ----
    float inv0 = 1.0f / l0, inv1 = 1.0f / l1;
    float* ybase = g_y + ((size_t)(b * TT + qt)) * CC + h * DH;
    #pragma unroll
    for (int nf = 0; nf < 8; nf++) {
        int col = nf * 8 + 2 * t;
        int r0 = w * 16 + g;
        ybase[(size_t)r0       * CC + col]     = rndf(o[nf][0] * inv0);
        ybase[(size_t)r0       * CC + col + 1] = rndf(o[nf][1] * inv0);
        ybase[(size_t)(r0 + 8) * CC + col]     = rndf(o[nf][2] * inv1);
        ybase[(size_t)(r0 + 8) * CC + col + 1] = rndf(o[nf][3] * inv1);
    }
}

// ---------------- block reductions ----------------
__device__ __forceinline__ float block_reduce_sum(float v, float* sm) {
    #pragma unroll
    for (int o = 16; o; o >>= 1) v += __shfl_xor_sync(0xffffffffu, v, o);
    int w = threadIdx.x >> 5;
    if ((threadIdx.x & 31) == 0) sm[w] = v;
    __syncthreads();
    if (threadIdx.x < 32) {
        float x = (threadIdx.x < 8) ? sm[threadIdx.x] : 0.0f;
        #pragma unroll
        for (int o = 4; o; o >>= 1) x += __shfl_xor_sync(0xffffffffu, x, o);
        if (threadIdx.x == 0) sm[0] = x;
    }
    __syncthreads();
    float r = sm[0];
    __syncthreads();
    return r;
}

// ---------------- embedding ----------------
__global__ void embed_k(const int* __restrict__ idx, const float* __restrict__ tok,
                        const float* __restrict__ pos) {
    int i = blockIdx.x * blockDim.x + threadIdx.x;
    int m = i / CC, c = i - m * CC;
    int t = m & (TT - 1);
    g_x[i] = tok[idx[m] * CC + c] + pos[t * CC + c];
}

// ---------------- layernorm (output rounded to tf32) ----------------
__global__ void ln_k(const float* __restrict__ in, const float* __restrict__ gam,
                     const float* __restrict__ bet, float* __restrict__ out) {
    __shared__ float sm[8];
    int row = blockIdx.x;
    const float* x = in + (size_t)row * CC;
    int t = threadIdx.x;
    float v0 = x[t], v1 = x[t + 256];
    float mean = block_reduce_sum(v0 + v1, sm) * (1.0f / CC);
    float d0 = v0 - mean, d1 = v1 - mean;
    float var = block_reduce_sum(d0 * d0 + d1 * d1, sm) * (1.0f / CC);
    float rstd = rsqrtf(var + 1e-5f);
    float* o = out + (size_t)row * CC;
    o[t]       = rndf(d0 * rstd * gam[t]       + bet[t]);
    o[t + 256] = rndf(d1 * rstd * gam[t + 256] + bet[t + 256]);
}

// ---------------- host orchestration ----------------
extern "C" void kernel_launch(void* const* d_in, const int* in_sizes, int n_in,
                              void* d_out, int out_size) {
    const int*   idx  = (const int*)  d_in[0];
    const float* tok  = (const float*)d_in[1];
    const float* pos  = (const float*)d_in[2];
    const float* ln1g = (const float*)d_in[3];
    const float* ln1b = (const float*)d_in[4];
    const float* Wq   = (const float*)d_in[5];
    const float* bq   = (const float*)d_in[6];
    const float* Wk   = (const float*)d_in[7];
    const float* bk   = (const float*)d_in[8];
    const float* Wv   = (const float*)d_in[9];
    const float* bv   = (const float*)d_in[10];
    const float* Wp   = (const float*)d_in[11];
    const float* bp   = (const float*)d_in[12];
    const float* ln2g = (const float*)d_in[13];
    const float* ln2b = (const float*)d_in[14];
    const float* W1   = (const float*)d_in[15];
    const float* b1   = (const float*)d_in[16];
    const float* W2   = (const float*)d_in[17];
    const float* b2   = (const float*)d_in[18];
    const float* lnfg = (const float*)d_in[19];
    const float* lnfb = (const float*)d_in[20];
    const float* Wh   = (const float*)d_in[21];
    float* out = (float*)d_out;

    float *px, *pxn, *pqkv, *py, *ph;
    float *pwqkv, *pbqkv, *pwp, *pw1, *pw2, *pwh;
    cudaGetSymbolAddress((void**)&px,    g_x);
    cudaGetSymbolAddress((void**)&pxn,   g_xn);
    cudaGetSymbolAddress((void**)&pqkv,  g_qkv);
    cudaGetSymbolAddress((void**)&py,    g_y);
    cudaGetSymbolAddress((void**)&ph,    g_h);
    cudaGetSymbolAddress((void**)&pwqkv, g_wqkv);
    cudaGetSymbolAddress((void**)&pbqkv, g_bqkv);
    cudaGetSymbolAddress((void**)&pwp,   g_wp);
    cudaGetSymbolAddress((void**)&pw1,   g_w1);
    cudaGetSymbolAddress((void**)&pw2,   g_w2);
    cudaGetSymbolAddress((void**)&pwh,   g_wh);

    cudaFuncSetAttribute(mma_gemm_k<false,false>,
                         cudaFuncAttributeMaxDynamicSharedMemorySize, GEMM_SMEM);
    cudaFuncSetAttribute(mma_gemm_k<false,true>,
                         cudaFuncAttributeMaxDynamicSharedMemorySize, GEMM_SMEM);
    cudaFuncSetAttribute(mma_gemm_k<true,true>,
                         cudaFuncAttributeMaxDynamicSharedMemorySize, GEMM_SMEM);
    cudaFuncSetAttribute(flash_k,
                         cudaFuncAttributeMaxDynamicSharedMemorySize, FL_SMEM);

    // weight preprocessing (tf32 pre-rounding + QKV concat)
    prep_wqkv_k<<<(2 * CC * CC + 255) / 256, 256>>>(Wq, Wk, Wv);
    prep_bqkv_k<<<(2 * CC + 255) / 256, 256>>>(bq, bk, bv);
    prep_round_k<<<(2 * CC * CC + 255) / 256, 256>>>(Wp, pwp, 2 * CC * CC);
    prep_round_k<<<(2 * CC * CF + 255) / 256, 256>>>(W1, pw1, 2 * CC * CF);
    prep_round_k<<<(2 * CF * CC + 255) / 256, 256>>>(W2, pw2, 2 * CF * CC);
    prep_round_k<<<(CC * VV + 255) / 256, 256>>>(Wh, pwh, CC * VV);

    embed_k<<<(MTOK * CC) / 256, 256>>>(idx, tok, pos);

    dim3 gQKV(C3 / 128, MTOK / 128);    // (12, 32)
    dim3 gCC(CC / 128, MTOK / 128);     // (4, 32)
    dim3 gCF(CF / 128, MTOK / 128);     // (16, 32)
    dim3 gFL(TT / 128, BB * HH);        // (4, 64)

    for (int step = 0; step < NSTEPS; step++) {
        for (int l = 0; l < 2; l++) {
            size_t bo  = (size_t)l * CC;
            size_t b1o = (size_t)l * CF;

            ln_k<<<MTOK, 256>>>(px, ln1g + bo, ln1b + bo, pxn);
            mma_gemm_k<false,true><<<gQKV, 256, GEMM_SMEM>>>(
                pxn, pwqkv + (size_t)l * CC * C3, pbqkv + (size_t)l * C3,
                nullptr, pqkv, MTOK, C3, CC);
            flash_k<<<gFL, 256, FL_SMEM>>>();
            // x = x + y @ Wp + bp
            mma_gemm_k<false,false><<<gCC, 256, GEMM_SMEM>>>(
                py, pwp + (size_t)l * CC * CC, bp + bo, px, px, MTOK, CC, CC);

            ln_k<<<MTOK, 256>>>(px, ln2g + bo, ln2b + bo, pxn);
            mma_gemm_k<true,true><<<gCF, 256, GEMM_SMEM>>>(
                pxn, pw1 + (size_t)l * CC * CF, b1 + b1o, nullptr, ph, MTOK, CF, CC);
            // x = x + h @ W2 + b2
            mma_gemm_k<false,false><<<gCC, 256, GEMM_SMEM>>>(
                ph, pw2 + (size_t)l * CF * CC, b2 + bo, px, px, MTOK, CC, CF);
        }
    }

    ln_k<<<MTOK, 256>>>(px, lnfg, lnfb, pxn);
    mma_gemm_k<false,false><<<dim3(VV / 128, MTOK / 128), 256, GEMM_SMEM>>>(
        pxn, pwh, nullptr, nullptr, out, MTOK, VV, CC);
}